// round 2
// baseline (speedup 1.0000x reference)
#include <cuda_runtime.h>
#include <float.h>

// SparseSoftmax: masked softmax over last axis.
// features: (32, 2048, 2048) fp32, OD: same shape int32 (mask = OD != 0).
// One CTA per row. 256 threads x 8 elements in registers.
// R2: streaming cache hints (pure-stream data, no reuse) + 2 barriers instead of 4.

#define ROW_LEN 2048
#define THREADS 256
#define NWARPS  (THREADS / 32)

__global__ __launch_bounds__(THREADS, 8)
void sparse_softmax_kernel(const float* __restrict__ f,
                           const int* __restrict__ od,
                           float* __restrict__ out)
{
    const int row = blockIdx.x;
    const size_t base = (size_t)row * ROW_LEN;
    const float4* __restrict__ f4 = reinterpret_cast<const float4*>(f + base);
    const int4*   __restrict__ o4 = reinterpret_cast<const int4*>(od + base);
    float4* __restrict__ out4 = reinterpret_cast<float4*>(out + base);

    const int t = threadIdx.x;
    const int warp = t >> 5;
    const int lane = t & 31;

    // Streaming loads: this data is touched exactly once — evict-first.
    float4 v0 = __ldcs(&f4[t]);
    float4 v1 = __ldcs(&f4[t + THREADS]);
    int4   m0 = __ldcs(&o4[t]);
    int4   m1 = __ldcs(&o4[t + THREADS]);

    float vals[8] = {v0.x, v0.y, v0.z, v0.w, v1.x, v1.y, v1.z, v1.w};
    int   msk [8] = {m0.x, m0.y, m0.z, m0.w, m1.x, m1.y, m1.z, m1.w};

    __shared__ float smax[NWARPS];
    __shared__ float ssum[NWARPS];

    // --- local + warp max over unmasked lanes ---
    float mx = -FLT_MAX;
    #pragma unroll
    for (int i = 0; i < 8; i++)
        if (msk[i] != 0) mx = fmaxf(mx, vals[i]);
    #pragma unroll
    for (int o = 16; o > 0; o >>= 1)
        mx = fmaxf(mx, __shfl_xor_sync(0xffffffffu, mx, o));
    if (lane == 0) smax[warp] = mx;
    __syncthreads();

    // Every thread reduces the 8 partials itself (broadcast LDS, no 2nd barrier).
    float rowmax = smax[0];
    #pragma unroll
    for (int w = 1; w < NWARPS; w++) rowmax = fmaxf(rowmax, smax[w]);

    // --- exp + sum (exp only on unmasked lanes; vals - rowmax <= 0) ---
    float p[8];
    float sum = 0.0f;
    #pragma unroll
    for (int i = 0; i < 8; i++) {
        float e = (msk[i] != 0) ? __expf(vals[i] - rowmax) : 0.0f;
        p[i] = e;
        sum += e;
    }
    #pragma unroll
    for (int o = 16; o > 0; o >>= 1)
        sum += __shfl_xor_sync(0xffffffffu, sum, o);
    if (lane == 0) ssum[warp] = sum;
    __syncthreads();

    float s = ssum[0];
    #pragma unroll
    for (int w = 1; w < NWARPS; w++) s += ssum[w];
    const float inv = (s > 0.0f) ? (1.0f / s) : 0.0f;   // fully-masked row -> zeros

    // --- normalize + streaming write ---
    float4 r0 = make_float4(p[0] * inv, p[1] * inv, p[2] * inv, p[3] * inv);
    float4 r1 = make_float4(p[4] * inv, p[5] * inv, p[6] * inv, p[7] * inv);
    __stcs(&out4[t],           r0);
    __stcs(&out4[t + THREADS], r1);
}

extern "C" void kernel_launch(void* const* d_in, const int* in_sizes, int n_in,
                              void* d_out, int out_size)
{
    const float* features = (const float*)d_in[0];
    const int*   OD       = (const int*)d_in[1];
    float*       out      = (float*)d_out;

    const int rows = in_sizes[0] / ROW_LEN;   // 32*2048 = 65536
    sparse_softmax_kernel<<<rows, THREADS>>>(features, OD, out);
}